// round 9
// baseline (speedup 1.0000x reference)
#include <cuda_runtime.h>
#include <cuda_fp16.h>
#include <math.h>
#include <stdint.h>

// Problem constants (fixed by setup_inputs)
#define DIM   256
#define NHEAD 8
#define DHEAD 32
#define LQ    16320
#define PROJN 768   // [cso 256 | tso 256 | caw 128 | taw 128]

// Scratch (device globals)
__device__ __half g_value[LQ * DIM];
__device__ float  g_proj [LQ * PROJN];
__device__ float  g_mid  [LQ * DIM];

// ---------------- FP16 tensor-core GEMM v4 (m16n8k16) ----------------------
// C = A(M x 256) * B(256 x N) + bias, fp32 accum. Block tile 128x128, BK=16.
// 256 threads = 8 warps (2x4), warp tile 64x32 = 4x4 m16n8k16 atoms.
// ldmatrix fragment loads; padded row-major half tiles (conflict-free phases).
// M=16320 handled with grid.y=128: last block clamps A rows, guards C stores.
#define GBM 128
#define GBN 128
#define AROW 40    // halfs per A row (16 + pad -> 40 for bank spread)
#define BROW 136   // halfs per B row (128 + 8 pad)

struct Seg {
    const float* A;
    const float* B;
    const float* bias;
    float*  Cf;
    __half* Ch;
    int ldb, boff, ldc, cn0, ishalf;
};
struct SegArr { Seg s[8]; };

__device__ __forceinline__ uint32_t pack2(float a, float b) {
    __half2 h = __floats2half2_rn(a, b);
    return *(uint32_t*)&h;
}
__device__ __forceinline__ uint4 pack8(float4 v0, float4 v1) {
    uint4 u;
    u.x = pack2(v0.x, v0.y); u.y = pack2(v0.z, v0.w);
    u.z = pack2(v1.x, v1.y); u.w = pack2(v1.z, v1.w);
    return u;
}
__device__ __forceinline__ void ldsm4(uint32_t* r, uint32_t addr) {
    asm volatile("ldmatrix.sync.aligned.m8n8.x4.shared.b16 {%0,%1,%2,%3}, [%4];"
        : "=r"(r[0]), "=r"(r[1]), "=r"(r[2]), "=r"(r[3]) : "r"(addr));
}
__device__ __forceinline__ void ldsm4t(uint32_t* r, uint32_t addr) {
    asm volatile("ldmatrix.sync.aligned.m8n8.x4.trans.shared.b16 {%0,%1,%2,%3}, [%4];"
        : "=r"(r[0]), "=r"(r[1]), "=r"(r[2]), "=r"(r[3]) : "r"(addr));
}

__global__ __launch_bounds__(256, 2) void mma_gemm_seg(SegArr sa)
{
    __shared__ __half As[GBM * AROW];   // 10240 B
    __shared__ __half Bs[16 * BROW];    // 4352 B

    const Seg sg = sa.s[blockIdx.x];
    const int tid = threadIdx.x;
    const int bm  = blockIdx.y * GBM;

    const int lane = tid & 31, wid = tid >> 5;
    const int wm = wid >> 2, wn = wid & 3;
    const int g = lane >> 2, t = lane & 3;

    // ---- fill mappings ----
    const int arf = tid >> 1;             // A row 0..127
    const int acf = (tid & 1) << 3;       // A col octet 0/8
    const int arg = min(bm + arf, LQ - 1);
    const float* Ag = sg.A + (size_t)arg * 256 + acf;
    __half* As_st = As + arf * AROW + acf;

    const int brf = tid >> 4;             // B k-row 0..15
    const int bcf = (tid & 15) << 3;      // B col octet
    const float* Bg = sg.B + (size_t)brf * sg.ldb + sg.boff + bcf;
    __half* Bs_st = Bs + brf * BROW + bcf;

    // ---- ldmatrix lane addresses ----
    const uint32_t as_addr = (uint32_t)__cvta_generic_to_shared(As);
    const uint32_t bs_addr = (uint32_t)__cvta_generic_to_shared(Bs);
    const int arow = wm * 64 + (lane & 15);       // + mi*16
    const int acol = (lane >> 4) * 8;
    const int brow = lane & 15;
    const int bcol = wn * 32 + (lane >> 4) * 8;   // + nip*16
    const uint32_t aaddr0 = as_addr + (uint32_t)((arow * AROW + acol) * 2);
    const uint32_t baddr0 = bs_addr + (uint32_t)((brow * BROW + bcol) * 2);

    float acc[4][4][4] = {};

    // prefetch slab 0
    float4 av0 = *(const float4*)(Ag);
    float4 av1 = *(const float4*)(Ag + 4);
    float4 bv0 = *(const float4*)(Bg);
    float4 bv1 = *(const float4*)(Bg + 4);

    #pragma unroll
    for (int k0 = 0; k0 < 256; k0 += 16) {
        *(uint4*)As_st = pack8(av0, av1);
        *(uint4*)Bs_st = pack8(bv0, bv1);
        __syncthreads();

        if (k0 < 240) {
            av0 = *(const float4*)(Ag + k0 + 16);
            av1 = *(const float4*)(Ag + k0 + 20);
            bv0 = *(const float4*)(Bg + (size_t)(k0 + 16) * sg.ldb);
            bv1 = *(const float4*)(Bg + (size_t)(k0 + 16) * sg.ldb + 4);
        }

        uint32_t a[4][4], b[2][4];
        #pragma unroll
        for (int mi = 0; mi < 4; ++mi)
            ldsm4(a[mi], aaddr0 + (uint32_t)(mi * 16 * AROW * 2));
        #pragma unroll
        for (int nip = 0; nip < 2; ++nip)
            ldsm4t(b[nip], baddr0 + (uint32_t)(nip * 16 * 2));

        #pragma unroll
        for (int mi = 0; mi < 4; ++mi)
            #pragma unroll
            for (int ni = 0; ni < 4; ++ni) {
                uint32_t b0 = b[ni >> 1][(ni & 1) * 2];
                uint32_t b1 = b[ni >> 1][(ni & 1) * 2 + 1];
                asm volatile(
                    "mma.sync.aligned.m16n8k16.row.col.f32.f16.f16.f32 "
                    "{%0,%1,%2,%3}, {%4,%5,%6,%7}, {%8,%9}, {%0,%1,%2,%3};"
                    : "+f"(acc[mi][ni][0]), "+f"(acc[mi][ni][1]),
                      "+f"(acc[mi][ni][2]), "+f"(acc[mi][ni][3])
                    : "r"(a[mi][0]), "r"(a[mi][1]), "r"(a[mi][2]), "r"(a[mi][3]),
                      "r"(b0), "r"(b1));
            }
        __syncthreads();
    }

    // ---- epilogue (guard rows >= LQ in the last block) ----
    #pragma unroll
    for (int mi = 0; mi < 4; ++mi) {
        int rbase = bm + wm * 64 + mi * 16;
        if (rbase >= LQ) continue;
        int row0 = rbase + g;
        #pragma unroll
        for (int ni = 0; ni < 4; ++ni) {
            int lcol = wn * 32 + ni * 8 + t * 2;
            float2 bv2 = *(const float2*)(sg.bias + sg.boff + lcol);
            float v00 = acc[mi][ni][0] + bv2.x, v01 = acc[mi][ni][1] + bv2.y;
            float v10 = acc[mi][ni][2] + bv2.x, v11 = acc[mi][ni][3] + bv2.y;
            if (sg.ishalf) {
                *(__half2*)(sg.Ch + (size_t)row0 * sg.ldc + sg.cn0 + lcol)       = __floats2half2_rn(v00, v01);
                *(__half2*)(sg.Ch + (size_t)(row0 + 8) * sg.ldc + sg.cn0 + lcol) = __floats2half2_rn(v10, v11);
            } else {
                *(float2*)(sg.Cf + (size_t)row0 * sg.ldc + sg.cn0 + lcol)       = make_float2(v00, v01);
                *(float2*)(sg.Cf + (size_t)(row0 + 8) * sg.ldc + sg.cn0 + lcol) = make_float2(v10, v11);
            }
        }
    }
}

// ---------------- Deformable sampling + softmax (v3, unchanged) ----------------
__global__ __launch_bounds__(256) void deform_kernel(
    const float* __restrict__ proj,
    const __half* __restrict__ value,
    const float* __restrict__ refp,
    const float* __restrict__ toff,
    float* __restrict__ mid)
{
    __shared__ float4 smw[256];
    __shared__ int4   sma[256];

    const int q    = blockIdx.x;
    const int warp = threadIdx.x >> 5;
    const int lane = threadIdx.x & 31;
    const int h = warp;
    const int l = lane >> 3;
    const int p = lane & 7;

    const int   Wl[4]  = {64, 32, 16, 8};
    const int   THl[4] = {192, 96, 48, 24};
    const int   STl[4] = {0, 12288, 15360, 16128};
    const int   Wv = Wl[l], TH = THl[l], start = STl[l];
    const float invW = 1.0f / (float)Wv, invTH = 1.0f / (float)TH;

    const float* prow = proj + (size_t)q * PROJN;

    int logit_col = (p < 4) ? (512 + h * 16 + l * 4 + p)
                            : (640 + h * 16 + l * 4 + (p - 4));
    float logit = prow[logit_col];
    float mx = logit;
    #pragma unroll
    for (int off = 16; off; off >>= 1) mx = fmaxf(mx, __shfl_xor_sync(0xffffffffu, mx, off));
    float e = __expf(logit - mx);
    float s = e;
    #pragma unroll
    for (int off = 16; off; off >>= 1) s += __shfl_xor_sync(0xffffffffu, s, off);
    float attnw = e / s;

    float rx = refp[q * 8 + l * 2 + 0];
    float ry = refp[q * 8 + l * 2 + 1];
    float ox, oy;
    if (p < 4) {
        int col = ((h * 4 + l) * 4 + p) * 2;
        ox = prow[col + 0] * invW;
        oy = prow[col + 1] * invTH;
    } else {
        int tw = (p - 4) >> 1, tp = (p - 4) & 1;
        int col = 256 + (((h * 4 + l) * 2 + tw) * 2 + tp) * 2;
        int tob = ((q * 4 + l) * 2 + tw) * 2;
        ox = toff[tob + 0] + prow[col + 0] * invW;
        oy = toff[tob + 1] + prow[col + 1] * invTH;
    }
    float x = (rx + ox) * (float)Wv - 0.5f;
    float y = (ry + oy) * (float)TH - 0.5f;

    float x0f = floorf(x), y0f = floorf(y);
    float lx = x - x0f, ly = y - y0f;
    int x0 = (int)x0f, y0 = (int)y0f;
    int x1 = x0 + 1,   y1 = y0 + 1;

    bool ix0 = (x0 >= 0) & (x0 < Wv);
    bool ix1 = (x1 >= 0) & (x1 < Wv);
    bool iy0 = (y0 >= 0) & (y0 < TH);
    bool iy1 = (y1 >= 0) & (y1 < TH);
    int cx0 = min(max(x0, 0), Wv - 1);
    int cx1 = min(max(x1, 0), Wv - 1);
    int cy0 = min(max(y0, 0), TH - 1);
    int cy1 = min(max(y1, 0), TH - 1);

    float4 w;
    w.x = attnw * (1.f - lx) * (1.f - ly) * (float)(ix0 & iy0);
    w.y = attnw * lx         * (1.f - ly) * (float)(ix1 & iy0);
    w.z = attnw * (1.f - lx) * ly         * (float)(ix0 & iy1);
    w.w = attnw * lx         * ly         * (float)(ix1 & iy1);

    const int hbase = h * DHEAD;
    int4 a;
    a.x = (start + cy0 * Wv + cx0) * DIM + hbase;
    a.y = (start + cy0 * Wv + cx1) * DIM + hbase;
    a.z = (start + cy1 * Wv + cx0) * DIM + hbase;
    a.w = (start + cy1 * Wv + cx1) * DIM + hbase;

    smw[threadIdx.x] = w;
    sma[threadIdx.x] = a;
    __syncwarp();

    const int p2 = lane >> 4;
    const int c  = (lane >> 2) & 3;
    const int o  = lane & 3;
    const int ob = o << 3;

    const int* aw_i   = (const int*)sma;
    const float* aw_f = (const float*)smw;
    const int sbase4 = (warp << 5) << 2;

    float acc[8] = {};
    #pragma unroll
    for (int i = 0; i < 16; ++i) {
        int widx = sbase4 + ((i * 2 + p2) << 2) + c;
        int   addr = aw_i[widx];
        float wgt  = aw_f[widx];
        uint4 v = __ldcg((const uint4*)(value + addr + ob));
        float2 f0 = __half22float2(*(__half2*)&v.x);
        float2 f1 = __half22float2(*(__half2*)&v.y);
        float2 f2 = __half22float2(*(__half2*)&v.z);
        float2 f3 = __half22float2(*(__half2*)&v.w);
        acc[0] += wgt * f0.x; acc[1] += wgt * f0.y;
        acc[2] += wgt * f1.x; acc[3] += wgt * f1.y;
        acc[4] += wgt * f2.x; acc[5] += wgt * f2.y;
        acc[6] += wgt * f3.x; acc[7] += wgt * f3.y;
    }
    #pragma unroll
    for (int j = 0; j < 8; ++j) {
        acc[j] += __shfl_xor_sync(0xffffffffu, acc[j], 4);
        acc[j] += __shfl_xor_sync(0xffffffffu, acc[j], 8);
        acc[j] += __shfl_xor_sync(0xffffffffu, acc[j], 16);
    }
    if (lane < 4) {
        float* dst = mid + (size_t)q * DIM + hbase + (lane << 3);
        *(float4*)(dst)     = make_float4(acc[0], acc[1], acc[2], acc[3]);
        *(float4*)(dst + 4) = make_float4(acc[4], acc[5], acc[6], acc[7]);
    }
}

// ---------------- launch ----------------
extern "C" void kernel_launch(void* const* d_in, const int* in_sizes, int n_in,
                              void* d_out, int out_size)
{
    const float* query = (const float*)d_in[0];
    const float* refp  = (const float*)d_in[1];
    const float* toff  = (const float*)d_in[2];
    const float* inpf  = (const float*)d_in[3];
    const float* W_so  = (const float*)d_in[6];
    const float* b_so  = (const float*)d_in[7];
    const float* W_tso = (const float*)d_in[8];
    const float* b_tso = (const float*)d_in[9];
    const float* W_aw  = (const float*)d_in[10];
    const float* b_aw  = (const float*)d_in[11];
    const float* W_taw = (const float*)d_in[12];
    const float* b_taw = (const float*)d_in[13];
    const float* W_v   = (const float*)d_in[14];
    const float* b_v   = (const float*)d_in[15];
    const float* W_o   = (const float*)d_in[16];
    const float* b_o   = (const float*)d_in[17];
    float* out = (float*)d_out;

    __half* value; float *proj, *mid;
    cudaGetSymbolAddress((void**)&value, g_value);
    cudaGetSymbolAddress((void**)&proj,  g_proj);
    cudaGetSymbolAddress((void**)&mid,   g_mid);

    const int MB = (LQ + GBM - 1) / GBM;  // 128
    dim3 blk(256);

    // (1) fused value + projections GEMM (8 segments)
    {
        SegArr sa{};
        for (int i = 0; i < 2; ++i) {
            sa.s[i].A = inpf; sa.s[i].B = W_v; sa.s[i].bias = b_v;
            sa.s[i].Ch = value; sa.s[i].ldb = 256; sa.s[i].boff = i * 128;
            sa.s[i].ldc = DIM; sa.s[i].cn0 = i * 128; sa.s[i].ishalf = 1;
        }
        for (int i = 0; i < 2; ++i) {
            sa.s[2 + i].A = query; sa.s[2 + i].B = W_so; sa.s[2 + i].bias = b_so;
            sa.s[2 + i].Cf = proj; sa.s[2 + i].ldb = 256; sa.s[2 + i].boff = i * 128;
            sa.s[2 + i].ldc = PROJN; sa.s[2 + i].cn0 = i * 128; sa.s[2 + i].ishalf = 0;
            sa.s[4 + i].A = query; sa.s[4 + i].B = W_tso; sa.s[4 + i].bias = b_tso;
            sa.s[4 + i].Cf = proj; sa.s[4 + i].ldb = 256; sa.s[4 + i].boff = i * 128;
            sa.s[4 + i].ldc = PROJN; sa.s[4 + i].cn0 = 256 + i * 128; sa.s[4 + i].ishalf = 0;
        }
        sa.s[6].A = query; sa.s[6].B = W_aw; sa.s[6].bias = b_aw;
        sa.s[6].Cf = proj; sa.s[6].ldb = 128; sa.s[6].boff = 0;
        sa.s[6].ldc = PROJN; sa.s[6].cn0 = 512; sa.s[6].ishalf = 0;
        sa.s[7].A = query; sa.s[7].B = W_taw; sa.s[7].bias = b_taw;
        sa.s[7].Cf = proj; sa.s[7].ldb = 128; sa.s[7].boff = 0;
        sa.s[7].ldc = PROJN; sa.s[7].cn0 = 640; sa.s[7].ishalf = 0;
        mma_gemm_seg<<<dim3(8, MB), blk>>>(sa);
    }
    // (2) deform
    deform_kernel<<<LQ, 256>>>(proj, value, refp, toff, mid);
    // (3) out = mid @ W_o + b_o
    {
        SegArr sa{};
        for (int i = 0; i < 2; ++i) {
            sa.s[i].A = mid; sa.s[i].B = W_o; sa.s[i].bias = b_o;
            sa.s[i].Cf = out; sa.s[i].ldb = 256; sa.s[i].boff = i * 128;
            sa.s[i].ldc = DIM; sa.s[i].cn0 = i * 128; sa.s[i].ishalf = 0;
        }
        mma_gemm_seg<<<dim3(2, MB), blk>>>(sa);
    }
}